// round 3
// baseline (speedup 1.0000x reference)
#include <cuda_runtime.h>

// EventMessagePassingEdge: out = relu([h[src]|e_h|h[dst]]@W1+b1 | ext] @ W2 + b2)
// Folded:  out = relu( P[src] + Q[dst] + e_h@(W1b@W2a) + ext@W2b + (b1@W2a+b2) )
//   P = h @ (W1a@W2a), Q = h @ (W1c@W2a)   (per-node precompute, 50k x 64)
// All fp32, inner products via packed fma.rn.f32x2 (2x FFMA rate on sm_103a).

#define N_NODES 50000
#define N_EDGES 800000
#define HID 64
#define EXT 32

typedef unsigned long long ull;

// ---- device scratch (no allocations allowed) ----
__device__ float g_P[N_NODES * HID];            // h @ (W1a@W2a)
__device__ float g_Q[N_NODES * HID];            // h @ (W1c@W2a)
__device__ float g_M[(HID + EXT) * HID];        // rows 0..63: W1b@W2a, rows 64..95: W2b
__device__ float g_Wn[HID * 2 * HID];           // [k][0..63]=W1a@W2a  [k][64..127]=W1c@W2a
__device__ float g_c[HID];                      // b1@W2a + b2

// ---- packed f32x2 helpers ----
__device__ __forceinline__ ull pk2(float lo, float hi) {
    ull r; asm("mov.b64 %0, {%1, %2};" : "=l"(r) : "f"(lo), "f"(hi)); return r;
}
__device__ __forceinline__ void upk2(ull v, float& lo, float& hi) {
    asm("mov.b64 {%0, %1}, %2;" : "=f"(lo), "=f"(hi) : "l"(v));
}
__device__ __forceinline__ ull ffma2(ull a, ull b, ull c) {
    ull d; asm("fma.rn.f32x2 %0, %1, %2, %3;" : "=l"(d) : "l"(a), "l"(b), "l"(c)); return d;
}

// Rank-1 update: acc[0..63] += v * row[0..63]   (row is shared mem, 16B-aligned)
__device__ __forceinline__ void step64(float v, const float* row, ull* acc) {
    ull vv = pk2(v, v);
    const ulonglong2* r = (const ulonglong2*)row;
#pragma unroll
    for (int j = 0; j < 16; j++) {
        ulonglong2 m = r[j];
        acc[2 * j]     = ffma2(vv, m.x, acc[2 * j]);
        acc[2 * j + 1] = ffma2(vv, m.y, acc[2 * j + 1]);
    }
}

// ---- Stage 0: fold weight matrices (tiny) ----
__global__ void prep_kernel(const float* __restrict__ W1, const float* __restrict__ b1,
                            const float* __restrict__ W2, const float* __restrict__ b2) {
    int t = blockIdx.x * blockDim.x + threadIdx.x;
    int stride = gridDim.x * blockDim.x;
    // W1 rows: [0..63]=A (src), [64..127]=B (e_h), [128..191]=C (dst). W2 rows: [0..63]=W2a, [64..95]=W2b.
    for (int i = t; i < HID * HID; i += stride) {             // Wsrc = W1a @ W2a
        int k = i >> 6, j = i & 63;
        float s = 0.f;
        for (int x = 0; x < HID; x++) s += W1[k * HID + x] * W2[x * HID + j];
        g_Wn[k * 128 + j] = s;
    }
    for (int i = t; i < HID * HID; i += stride) {             // Wdst = W1c @ W2a
        int k = i >> 6, j = i & 63;
        float s = 0.f;
        for (int x = 0; x < HID; x++) s += W1[(128 + k) * HID + x] * W2[x * HID + j];
        g_Wn[k * 128 + 64 + j] = s;
    }
    for (int i = t; i < HID * HID; i += stride) {             // M1 = W1b @ W2a
        int k = i >> 6, j = i & 63;
        float s = 0.f;
        for (int x = 0; x < HID; x++) s += W1[(64 + k) * HID + x] * W2[x * HID + j];
        g_M[k * HID + j] = s;
    }
    for (int i = t; i < EXT * HID; i += stride) {             // copy W2b
        g_M[HID * HID + i] = W2[HID * HID + i];
    }
    for (int j = t; j < HID; j += stride) {                   // c = b1@W2a + b2
        float s = b2[j];
        for (int x = 0; x < HID; x++) s += b1[x] * W2[x * HID + j];
        g_c[j] = s;
    }
}

// ---- Stage 1: per-node precompute P,Q (2 threads per node) ----
__global__ void __launch_bounds__(256) node_kernel(const float* __restrict__ h) {
    __shared__ float sW[HID * 128];
    {
        float4* dst4 = (float4*)sW;
        const float4* src4 = (const float4*)g_Wn;
        for (int i = threadIdx.x; i < HID * 128 / 4; i += blockDim.x) dst4[i] = src4[i];
    }
    __syncthreads();

    int t = blockIdx.x * blockDim.x + threadIdx.x;
    int node = t >> 1;
    int sel = t & 1;                 // 0 -> P (src matrix), 1 -> Q (dst matrix)
    if (node >= N_NODES) return;

    ull acc[32];
#pragma unroll
    for (int j = 0; j < 32; j++) acc[j] = pk2(0.f, 0.f);

    const float4* hr = (const float4*)(h + (size_t)node * HID);
    const float* base = sW + sel * 64;
#pragma unroll 1
    for (int kk = 0; kk < 16; kk++) {
        float4 v = hr[kk];
        const float* r = base + (kk * 4) * 128;
        step64(v.x, r, acc);
        step64(v.y, r + 128, acc);
        step64(v.z, r + 256, acc);
        step64(v.w, r + 384, acc);
    }

    float* o = (sel ? g_Q : g_P) + (size_t)node * HID;
    float4* op = (float4*)o;
#pragma unroll
    for (int j = 0; j < 16; j++) {
        float a, b, c, d;
        upk2(acc[2 * j], a, b);
        upk2(acc[2 * j + 1], c, d);
        op[j] = make_float4(a, b, c, d);
    }
}

// ---- Stage 2: per-edge kernel (the hot loop) ----
__global__ void __launch_bounds__(256) edge_kernel(const float* __restrict__ e_h,
                                                   const float* __restrict__ ext,
                                                   const int* __restrict__ src,
                                                   const int* __restrict__ dst,
                                                   float* __restrict__ out) {
    __shared__ float sM[(HID + EXT) * HID];   // 96x64 = 24KB
    __shared__ float sc[HID];
    {
        float4* dst4 = (float4*)sM;
        const float4* src4 = (const float4*)g_M;
        for (int i = threadIdx.x; i < (HID + EXT) * HID / 4; i += blockDim.x) dst4[i] = src4[i];
    }
    if (threadIdx.x < HID) sc[threadIdx.x] = g_c[threadIdx.x];
    __syncthreads();

    int e = blockIdx.x * blockDim.x + threadIdx.x;
    if (e >= N_EDGES) return;

    int s = src[e];
    int d = dst[e];

    ull acc[32];
    {
        const float4* Pp = (const float4*)(g_P + (size_t)s * HID);
        const float4* Qp = (const float4*)(g_Q + (size_t)d * HID);
        const float4* Cp = (const float4*)sc;
#pragma unroll
        for (int j = 0; j < 16; j++) {
            float4 p = Pp[j], q = Qp[j], c = Cp[j];
            acc[2 * j]     = pk2(p.x + q.x + c.x, p.y + q.y + c.y);
            acc[2 * j + 1] = pk2(p.z + q.z + c.z, p.w + q.w + c.w);
        }
    }

    // e_h @ M1  (64 rank-1 steps)
    const float4* ehp = (const float4*)(e_h + (size_t)e * HID);
#pragma unroll 1
    for (int kk = 0; kk < 16; kk++) {
        float4 v = ehp[kk];
        const float* r = sM + (kk * 4) * HID;
        step64(v.x, r, acc);
        step64(v.y, r + 64, acc);
        step64(v.z, r + 128, acc);
        step64(v.w, r + 192, acc);
    }

    // ext @ W2b  (32 rank-1 steps, rows 64..95 of sM)
    const float4* exp4 = (const float4*)(ext + (size_t)e * EXT);
#pragma unroll 1
    for (int kk = 0; kk < 8; kk++) {
        float4 v = exp4[kk];
        const float* r = sM + (HID + kk * 4) * HID;
        step64(v.x, r, acc);
        step64(v.y, r + 64, acc);
        step64(v.z, r + 128, acc);
        step64(v.w, r + 192, acc);
    }

    // relu + store
    float4* op = (float4*)(out + (size_t)e * HID);
#pragma unroll
    for (int j = 0; j < 16; j++) {
        float a, b, c, d;
        upk2(acc[2 * j], a, b);
        upk2(acc[2 * j + 1], c, d);
        op[j] = make_float4(fmaxf(a, 0.f), fmaxf(b, 0.f), fmaxf(c, 0.f), fmaxf(d, 0.f));
    }
}

extern "C" void kernel_launch(void* const* d_in, const int* in_sizes, int n_in,
                              void* d_out, int out_size) {
    const float* h   = (const float*)d_in[0];
    const float* e_h = (const float*)d_in[1];
    const float* ext = (const float*)d_in[2];
    const float* W1  = (const float*)d_in[3];
    const float* b1  = (const float*)d_in[4];
    const float* W2  = (const float*)d_in[5];
    const float* b2  = (const float*)d_in[6];
    const int* src   = (const int*)d_in[7];
    const int* dst   = (const int*)d_in[8];
    float* out = (float*)d_out;

    prep_kernel<<<64, 128>>>(W1, b1, W2, b2);
    node_kernel<<<(2 * N_NODES + 255) / 256, 256>>>(h);
    edge_kernel<<<N_EDGES / 256, 256>>>(e_h, ext, src, dst, out);
}

// round 6
// speedup vs baseline: 2.2147x; 2.2147x over previous
#include <cuda_runtime.h>

// EventMessagePassingEdge: out = relu([h[src]|e_h|h[dst]]@W1+b1 | ext] @ W2 + b2)
// Folded:  out = relu( P[src] + Q[dst] + e_h@(W1b@W2a) + ext@W2b + (b1@W2a+b2) )
//   P = h @ (W1a@W2a), Q = h @ (W1c@W2a)   (per-node precompute, 50k x 64)
// Edge stage = register-tiled GEMM: CTA tile 128 edges x 64 outs, thread 4x8,
// packed fma.rn.f32x2 (2 FMA/lane/instr), gathers folded into accumulator init.

#define N_NODES 50000
#define N_EDGES 800000
#define HID 64
#define EXT 32
#define SA_STR 100            // 96 used + 4 pad -> conflict-free A broadcasts
#define SH_STR 68             // 64 used + 4 pad (node kernel)

typedef unsigned long long ull;

// ---- device scratch (no allocations allowed) ----
__device__ float g_P[N_NODES * HID];            // h @ (W1a@W2a)
__device__ float g_Q[N_NODES * HID];            // h @ (W1c@W2a)
__device__ float g_M[(HID + EXT) * HID];        // rows 0..63: W1b@W2a, rows 64..95: W2b
__device__ float g_Wn[HID * 2 * HID];           // [k][0..63]=W1a@W2a  [k][64..127]=W1c@W2a
__device__ float g_c[HID];                      // b1@W2a + b2

// ---- packed f32x2 helpers ----
__device__ __forceinline__ ull pk2(float lo, float hi) {
    ull r; asm("mov.b64 %0, {%1, %2};" : "=l"(r) : "f"(lo), "f"(hi)); return r;
}
__device__ __forceinline__ void upk2(ull v, float& lo, float& hi) {
    asm("mov.b64 {%0, %1}, %2;" : "=f"(lo), "=f"(hi) : "l"(v));
}
__device__ __forceinline__ ull splat(float v) {
    ull r; asm("mov.b64 %0, {%1, %1};" : "=l"(r) : "f"(v)); return r;
}
__device__ __forceinline__ ull ffma2(ull a, ull b, ull c) {
    ull d; asm("fma.rn.f32x2 %0, %1, %2, %3;" : "=l"(d) : "l"(a), "l"(b), "l"(c)); return d;
}
__device__ __forceinline__ float4 relu4(ull lo, ull hi) {
    float a, b, c, d;
    upk2(lo, a, b); upk2(hi, c, d);
    return make_float4(fmaxf(a, 0.f), fmaxf(b, 0.f), fmaxf(c, 0.f), fmaxf(d, 0.f));
}
__device__ __forceinline__ float4 pair4(ull lo, ull hi) {
    float a, b, c, d;
    upk2(lo, a, b); upk2(hi, c, d);
    return make_float4(a, b, c, d);
}

// ---- Stage 0: fold weight matrices (tiny) ----
__global__ void prep_kernel(const float* __restrict__ W1, const float* __restrict__ b1,
                            const float* __restrict__ W2, const float* __restrict__ b2) {
    int t = blockIdx.x * blockDim.x + threadIdx.x;
    int stride = gridDim.x * blockDim.x;
    for (int i = t; i < HID * HID; i += stride) {             // Wsrc = W1a @ W2a
        int k = i >> 6, j = i & 63;
        float s = 0.f;
        for (int x = 0; x < HID; x++) s += W1[k * HID + x] * W2[x * HID + j];
        g_Wn[k * 128 + j] = s;
    }
    for (int i = t; i < HID * HID; i += stride) {             // Wdst = W1c @ W2a
        int k = i >> 6, j = i & 63;
        float s = 0.f;
        for (int x = 0; x < HID; x++) s += W1[(128 + k) * HID + x] * W2[x * HID + j];
        g_Wn[k * 128 + 64 + j] = s;
    }
    for (int i = t; i < HID * HID; i += stride) {             // M1 = W1b @ W2a
        int k = i >> 6, j = i & 63;
        float s = 0.f;
        for (int x = 0; x < HID; x++) s += W1[(64 + k) * HID + x] * W2[x * HID + j];
        g_M[k * HID + j] = s;
    }
    for (int i = t; i < EXT * HID; i += stride) {             // copy W2b
        g_M[HID * HID + i] = W2[HID * HID + i];
    }
    for (int j = t; j < HID; j += stride) {                   // c = b1@W2a + b2
        float s = b2[j];
        for (int x = 0; x < HID; x++) s += b1[x] * W2[x * HID + j];
        g_c[j] = s;
    }
}

// ---- Stage 1: node precompute, tiled GEMM [50000x64] @ [64x128] -> P|Q ----
// CTA: 64 nodes x 128 outs. Thread: 4 nodes x 8 outs ({4og..},{64+4og..}).
__global__ void __launch_bounds__(256) node_kernel(const float* __restrict__ h) {
    extern __shared__ float smem[];
    float* sH = smem;                     // [64][SH_STR]
    float* sW = smem + 64 * SH_STR;       // [64][128]
    int tid = threadIdx.x;
    int og = tid & 15;                    // 16 out-groups of 4 (x2 halves)
    int ng = tid >> 4;                    // 16 node-groups
    int nb = blockIdx.x * 64;

    // stage h tile (guarded) and weights
    {
        const float4* h4 = (const float4*)h;
#pragma unroll
        for (int r = 0; r < 4; r++) {
            int t4 = tid + r * 256;
            int n = t4 >> 4, k = (t4 & 15) * 4;
            float4 v = make_float4(0.f, 0.f, 0.f, 0.f);
            if (nb + n < N_NODES) v = h4[(size_t)(nb + n) * 16 + (t4 & 15)];
            *(float4*)(sH + n * SH_STR + k) = v;
        }
        const float4* w4 = (const float4*)g_Wn;
#pragma unroll
        for (int r = 0; r < 8; r++) {
            int t4 = tid + r * 256;
            ((float4*)sW)[t4] = w4[t4];
        }
    }
    __syncthreads();

    ull acc[4][4];
#pragma unroll
    for (int i = 0; i < 4; i++)
#pragma unroll
        for (int j = 0; j < 4; j++) acc[i][j] = 0ull;

#pragma unroll 2
    for (int kk = 0; kk < 16; kk++) {
        float4 a[4];
#pragma unroll
        for (int i = 0; i < 4; i++)
            a[i] = *(const float4*)(sH + (ng + 16 * i) * SH_STR + kk * 4);
#pragma unroll
        for (int j = 0; j < 4; j++) {
            int k = kk * 4 + j;
            ulonglong2 b0 = *(const ulonglong2*)(sW + k * 128 + 4 * og);
            ulonglong2 b1 = *(const ulonglong2*)(sW + k * 128 + 64 + 4 * og);
#pragma unroll
            for (int i = 0; i < 4; i++) {
                float av = (j == 0) ? a[i].x : (j == 1) ? a[i].y : (j == 2) ? a[i].z : a[i].w;
                ull vv = splat(av);
                acc[i][0] = ffma2(vv, b0.x, acc[i][0]);
                acc[i][1] = ffma2(vv, b0.y, acc[i][1]);
                acc[i][2] = ffma2(vv, b1.x, acc[i][2]);
                acc[i][3] = ffma2(vv, b1.y, acc[i][3]);
            }
        }
    }

#pragma unroll
    for (int i = 0; i < 4; i++) {
        int n = nb + ng + 16 * i;
        if (n < N_NODES) {
            *(float4*)(g_P + (size_t)n * 64 + 4 * og) = pair4(acc[i][0], acc[i][1]);
            *(float4*)(g_Q + (size_t)n * 64 + 4 * og) = pair4(acc[i][2], acc[i][3]);
        }
    }
}

// ---- Stage 2: edge kernel, tiled GEMM [800000x96]@[96x64] + gathered init ----
// CTA: 128 edges x 64 outs. Thread: 4 edges (eg+32i) x 8 outs ({4og..},{32+4og..}).
__global__ void __launch_bounds__(256) edge_kernel(const float* __restrict__ e_h,
                                                   const float* __restrict__ ext,
                                                   const int* __restrict__ src,
                                                   const int* __restrict__ dst,
                                                   float* __restrict__ out) {
    extern __shared__ float smem[];
    float* sA = smem;                      // [128][SA_STR] : e_h|ext
    float* sB = smem + 128 * SA_STR;       // [96][64]      : M
    int tid = threadIdx.x;
    int og = tid & 7;                      // 8 out-groups
    int eg = tid >> 3;                     // 32 edge-groups
    size_t ebase = (size_t)blockIdx.x * 128;

    // accumulator init = P[src] + Q[dst] + c (gathered, fp32)
    ull acc[4][4];
    {
        float4 c0 = *(const float4*)(g_c + 4 * og);
        float4 c1 = *(const float4*)(g_c + 32 + 4 * og);
#pragma unroll
        for (int i = 0; i < 4; i++) {
            size_t E = ebase + eg + 32 * i;
            int s = src[E], d = dst[E];
            const float* Pr = g_P + (size_t)s * 64;
            const float* Qr = g_Q + (size_t)d * 64;
            float4 p0 = *(const float4*)(Pr + 4 * og);
            float4 p1 = *(const float4*)(Pr + 32 + 4 * og);
            float4 q0 = *(const float4*)(Qr + 4 * og);
            float4 q1 = *(const float4*)(Qr + 32 + 4 * og);
            acc[i][0] = pk2(p0.x + q0.x + c0.x, p0.y + q0.y + c0.y);
            acc[i][1] = pk2(p0.z + q0.z + c0.z, p0.w + q0.w + c0.w);
            acc[i][2] = pk2(p1.x + q1.x + c1.x, p1.y + q1.y + c1.y);
            acc[i][3] = pk2(p1.z + q1.z + c1.z, p1.w + q1.w + c1.w);
        }
    }

    // stage A (e_h rows 0..63 cols, ext rows 64..95 cols) and B
    {
        const float4* g4 = (const float4*)(e_h + ebase * 64);
#pragma unroll
        for (int r = 0; r < 8; r++) {
            int t4 = tid + r * 256;
            int e = t4 >> 4, k = (t4 & 15) * 4;
            *(float4*)(sA + e * SA_STR + k) = g4[t4];
        }
        const float4* x4 = (const float4*)(ext + ebase * 32);
#pragma unroll
        for (int r = 0; r < 4; r++) {
            int t4 = tid + r * 256;
            int e = t4 >> 3, k = 64 + (t4 & 7) * 4;
            *(float4*)(sA + e * SA_STR + k) = x4[t4];
        }
        const float4* m4 = (const float4*)g_M;
#pragma unroll
        for (int r = 0; r < 6; r++) {
            int t4 = tid + r * 256;
            ((float4*)sB)[t4] = m4[t4];
        }
    }
    __syncthreads();

    // mainloop: K = 96
#pragma unroll 2
    for (int kk = 0; kk < 24; kk++) {
        float4 a[4];
#pragma unroll
        for (int i = 0; i < 4; i++)
            a[i] = *(const float4*)(sA + (eg + 32 * i) * SA_STR + kk * 4);
#pragma unroll
        for (int j = 0; j < 4; j++) {
            int k = kk * 4 + j;
            ulonglong2 b0 = *(const ulonglong2*)(sB + k * 64 + 4 * og);
            ulonglong2 b1 = *(const ulonglong2*)(sB + k * 64 + 32 + 4 * og);
#pragma unroll
            for (int i = 0; i < 4; i++) {
                float av = (j == 0) ? a[i].x : (j == 1) ? a[i].y : (j == 2) ? a[i].z : a[i].w;
                ull vv = splat(av);
                acc[i][0] = ffma2(vv, b0.x, acc[i][0]);
                acc[i][1] = ffma2(vv, b0.y, acc[i][1]);
                acc[i][2] = ffma2(vv, b1.x, acc[i][2]);
                acc[i][3] = ffma2(vv, b1.y, acc[i][3]);
            }
        }
    }

    // relu + store
#pragma unroll
    for (int i = 0; i < 4; i++) {
        size_t E = ebase + eg + 32 * i;
        float* o = out + E * 64;
        *(float4*)(o + 4 * og) = relu4(acc[i][0], acc[i][1]);
        *(float4*)(o + 32 + 4 * og) = relu4(acc[i][2], acc[i][3]);
    }
}

extern "C" void kernel_launch(void* const* d_in, const int* in_sizes, int n_in,
                              void* d_out, int out_size) {
    const float* h   = (const float*)d_in[0];
    const float* e_h = (const float*)d_in[1];
    const float* ext = (const float*)d_in[2];
    const float* W1  = (const float*)d_in[3];
    const float* b1  = (const float*)d_in[4];
    const float* W2  = (const float*)d_in[5];
    const float* b2  = (const float*)d_in[6];
    const int* src   = (const int*)d_in[7];
    const int* dst   = (const int*)d_in[8];
    float* out = (float*)d_out;

    const int node_smem = (64 * SH_STR + 64 * 128) * 4;        // 50176 B
    const int edge_smem = (128 * SA_STR + 96 * 64) * 4;        // 75776 B
    cudaFuncSetAttribute(node_kernel, cudaFuncAttributeMaxDynamicSharedMemorySize, node_smem);
    cudaFuncSetAttribute(edge_kernel, cudaFuncAttributeMaxDynamicSharedMemorySize, edge_smem);

    prep_kernel<<<64, 128>>>(W1, b1, W2, b2);
    node_kernel<<<(N_NODES + 63) / 64, 256, node_smem>>>(h);
    edge_kernel<<<N_EDGES / 128, 256, edge_smem>>>(e_h, ext, src, dst, out);
}

// round 9
// speedup vs baseline: 2.5815x; 1.1656x over previous
#include <cuda_runtime.h>
#include <cstdint>

// EventMessagePassingEdge: out = relu([h[src]|e_h|h[dst]]@W1+b1 | ext] @ W2 + b2)
// Folded:  out = relu( P'[src] + Q[dst] + [e_h|ext] @ M )      (c folded into P')
// Edge stage = bf16 mma.sync (m16n8k16, sm_80-compatible HMMA) with 2-term operand
// splitting: A=A1+A2, B=B1+B2 (bf16); D ~= A1B1 + A1B2 + A2B1 accumulated in fp32.
// Tile: 128 edges x 64 outs per CTA, 8 warps (4x2), warp tile 32x32, K=96 x 3 passes.

#define N_NODES 50000
#define N_EDGES 800000
#define HID 64
#define EXT 32
#define SH_STR 68

typedef unsigned long long ull;
typedef unsigned int u32;

// ---- device scratch (no allocations allowed) ----
__device__ float g_P[N_NODES * HID];                 // h @ (W1a@W2a) + c
__device__ float g_Q[N_NODES * HID];                 // h @ (W1c@W2a)
__device__ float g_M[(HID + EXT) * HID];             // [k][n]
__device__ float g_Wn[HID * 2 * HID];                // node-stage weights
__device__ float g_c[HID];                           // b1@W2a + b2
__device__ __align__(16) u32 g_Mb[2][64 * 52];       // B split, n-major [64][104 bf16] (52 u32)

// ---- helpers ----
__device__ __forceinline__ u32 smem_u32(const void* p) {
    u32 a; asm("{ .reg .u64 t; cvta.to.shared.u64 t, %1; cvt.u32.u64 %0, t; }" : "=r"(a) : "l"(p));
    return a;
}
// split pair of fp32 into packed bf16 hi terms and packed bf16 residual terms
__device__ __forceinline__ void split2(float v0, float v1, u32& hi, u32& lo) {
    asm("cvt.rn.bf16x2.f32 %0, %1, %2;" : "=r"(hi) : "f"(v1), "f"(v0));   // lo16=v0, hi16=v1
    float h0 = __uint_as_float(hi << 16);
    float h1 = __uint_as_float(hi & 0xffff0000u);
    float r0 = v0 - h0, r1 = v1 - h1;
    asm("cvt.rn.bf16x2.f32 %0, %1, %2;" : "=r"(lo) : "f"(r1), "f"(r0));
}

// ---- packed f32x2 helpers (node kernel) ----
__device__ __forceinline__ ull pk2(float lo, float hi) {
    ull r; asm("mov.b64 %0, {%1, %2};" : "=l"(r) : "f"(lo), "f"(hi)); return r;
}
__device__ __forceinline__ void upk2(ull v, float& lo, float& hi) {
    asm("mov.b64 {%0, %1}, %2;" : "=f"(lo), "=f"(hi) : "l"(v));
}
__device__ __forceinline__ ull splat(float v) {
    ull r; asm("mov.b64 %0, {%1, %1};" : "=l"(r) : "f"(v)); return r;
}
__device__ __forceinline__ ull ffma2(ull a, ull b, ull c) {
    ull d; asm("fma.rn.f32x2 %0, %1, %2, %3;" : "=l"(d) : "l"(a), "l"(b), "l"(c)); return d;
}

// ---- mma.sync primitives ----
__device__ __forceinline__ void ldsm4(u32& r0, u32& r1, u32& r2, u32& r3, u32 addr) {
    asm volatile("ldmatrix.sync.aligned.m8n8.x4.shared.b16 {%0,%1,%2,%3}, [%4];"
                 : "=r"(r0), "=r"(r1), "=r"(r2), "=r"(r3) : "r"(addr));
}
__device__ __forceinline__ void mma16816(float* c, const u32* a, const u32* b) {
    asm volatile("mma.sync.aligned.m16n8k16.row.col.f32.bf16.bf16.f32 "
                 "{%0,%1,%2,%3}, {%4,%5,%6,%7}, {%8,%9}, {%0,%1,%2,%3};"
                 : "+f"(c[0]), "+f"(c[1]), "+f"(c[2]), "+f"(c[3])
                 : "r"(a[0]), "r"(a[1]), "r"(a[2]), "r"(a[3]), "r"(b[0]), "r"(b[1]));
}

// ---- Stage 0: fold weight matrices ----
__global__ void prep_kernel(const float* __restrict__ W1, const float* __restrict__ b1,
                            const float* __restrict__ W2, const float* __restrict__ b2) {
    int t = blockIdx.x * blockDim.x + threadIdx.x;
    int stride = gridDim.x * blockDim.x;
    for (int i = t; i < HID * HID; i += stride) {             // Wsrc = W1a @ W2a
        int k = i >> 6, j = i & 63;
        float s = 0.f;
        for (int x = 0; x < HID; x++) s += W1[k * HID + x] * W2[x * HID + j];
        g_Wn[k * 128 + j] = s;
    }
    for (int i = t; i < HID * HID; i += stride) {             // Wdst = W1c @ W2a
        int k = i >> 6, j = i & 63;
        float s = 0.f;
        for (int x = 0; x < HID; x++) s += W1[(128 + k) * HID + x] * W2[x * HID + j];
        g_Wn[k * 128 + 64 + j] = s;
    }
    for (int i = t; i < HID * HID; i += stride) {             // M1 = W1b @ W2a
        int k = i >> 6, j = i & 63;
        float s = 0.f;
        for (int x = 0; x < HID; x++) s += W1[(64 + k) * HID + x] * W2[x * HID + j];
        g_M[k * HID + j] = s;
    }
    for (int i = t; i < EXT * HID; i += stride) {             // copy W2b
        g_M[HID * HID + i] = W2[HID * HID + i];
    }
    for (int j = t; j < HID; j += stride) {                   // c = b1@W2a + b2
        float s = b2[j];
        for (int x = 0; x < HID; x++) s += b1[x] * W2[x * HID + j];
        g_c[j] = s;
    }
}

// ---- Stage 0b: split B = M^T into bf16 hi/lo, n-major [64][104], k-pairs packed ----
__global__ void prep2_kernel() {
    int t = blockIdx.x * blockDim.x + threadIdx.x;    // 64 n x 48 k-pairs
    if (t >= 64 * 48) return;
    int n = t & 63, kp = t >> 6;
    float v0 = g_M[(2 * kp) * HID + n];
    float v1 = g_M[(2 * kp + 1) * HID + n];
    u32 hi, lo;
    split2(v0, v1, hi, lo);
    g_Mb[0][n * 52 + kp] = hi;
    g_Mb[1][n * 52 + kp] = lo;
}

// ---- Stage 1: node precompute, tiled FFMA2 GEMM [50000x64] @ [64x128] -> P|Q ----
__global__ void __launch_bounds__(256) node_kernel(const float* __restrict__ h) {
    extern __shared__ char dynsmem[];
    float* sH = (float*)dynsmem;              // [64][SH_STR]
    float* sW = sH + 64 * SH_STR;             // [64][128]
    int tid = threadIdx.x;
    int og = tid & 15;
    int ng = tid >> 4;
    int nb = blockIdx.x * 64;

    {
        const float4* h4 = (const float4*)h;
#pragma unroll
        for (int r = 0; r < 4; r++) {
            int t4 = tid + r * 256;
            int n = t4 >> 4, k = (t4 & 15) * 4;
            float4 v = make_float4(0.f, 0.f, 0.f, 0.f);
            if (nb + n < N_NODES) v = h4[(size_t)(nb + n) * 16 + (t4 & 15)];
            *(float4*)(sH + n * SH_STR + k) = v;
        }
        const float4* w4 = (const float4*)g_Wn;
#pragma unroll
        for (int r = 0; r < 8; r++) {
            int t4 = tid + r * 256;
            ((float4*)sW)[t4] = w4[t4];
        }
    }
    __syncthreads();

    ull acc[4][4];
#pragma unroll
    for (int i = 0; i < 4; i++)
#pragma unroll
        for (int j = 0; j < 4; j++) acc[i][j] = 0ull;

#pragma unroll 2
    for (int kk = 0; kk < 16; kk++) {
        float4 a[4];
#pragma unroll
        for (int i = 0; i < 4; i++)
            a[i] = *(const float4*)(sH + (ng + 16 * i) * SH_STR + kk * 4);
#pragma unroll
        for (int j = 0; j < 4; j++) {
            int k = kk * 4 + j;
            ulonglong2 b0 = *(const ulonglong2*)(sW + k * 128 + 4 * og);
            ulonglong2 b1 = *(const ulonglong2*)(sW + k * 128 + 64 + 4 * og);
#pragma unroll
            for (int i = 0; i < 4; i++) {
                float av = (j == 0) ? a[i].x : (j == 1) ? a[i].y : (j == 2) ? a[i].z : a[i].w;
                ull vv = splat(av);
                acc[i][0] = ffma2(vv, b0.x, acc[i][0]);
                acc[i][1] = ffma2(vv, b0.y, acc[i][1]);
                acc[i][2] = ffma2(vv, b1.x, acc[i][2]);
                acc[i][3] = ffma2(vv, b1.y, acc[i][3]);
            }
        }
    }

    float4 c4 = *(const float4*)(g_c + 4 * og);   // fold bias-vector c into P
#pragma unroll
    for (int i = 0; i < 4; i++) {
        int n = nb + ng + 16 * i;
        if (n < N_NODES) {
            float a, b, c, d;
            upk2(acc[i][0], a, b); upk2(acc[i][1], c, d);
            *(float4*)(g_P + (size_t)n * 64 + 4 * og) =
                make_float4(a + c4.x, b + c4.y, c + c4.z, d + c4.w);
            upk2(acc[i][2], a, b); upk2(acc[i][3], c, d);
            *(float4*)(g_Q + (size_t)n * 64 + 4 * og) = make_float4(a, b, c, d);
        }
    }
}

// ---- Stage 2: edge kernel — bf16x3 mma.sync GEMM + gathered epilogue ----
// smem layout (bytes):
//   A1 @ 0      (128 x 208B = 26624)        bf16 [128][104], k contiguous
//   A2 @ 26624  (26624)
//   B1 @ 53248  (64 x 208B = 13312)         bf16 [64][104] n-major
//   B2 @ 66560  (13312)
//   idx @ 79872 (1024)                       src[128], dst[128]
//   staging (f32 128x64, XOR-staggered) overlays A1/A2 after the MMA phase.
#define ASTR 208
#define OFF_A1 0
#define OFF_A2 26624
#define OFF_B1 53248
#define OFF_B2 66560
#define OFF_IDX 79872
#define EDGE_SMEM 80896

__global__ void __launch_bounds__(256, 2) edge_kernel(const float* __restrict__ e_h,
                                                      const float* __restrict__ ext,
                                                      const int* __restrict__ src,
                                                      const int* __restrict__ dst,
                                                      float* __restrict__ out) {
    extern __shared__ char dynsmem[];
    char* smem = dynsmem;
    u32 sb = smem_u32(smem);
    int tid = threadIdx.x, wid = tid >> 5, lane = tid & 31;
    size_t ebase = (size_t)blockIdx.x * 128;
    int* sidx = (int*)(smem + OFF_IDX);
    int* didx = sidx + 128;

    // -- stage indices --
    if (tid < 128) sidx[tid] = src[ebase + tid];
    else didx[tid - 128] = dst[ebase + (tid - 128)];

    // -- stage A: load fp32, split into bf16 hi/lo tiles --
    {
        const float4* g4 = (const float4*)(e_h + ebase * 64);     // k 0..63
#pragma unroll
        for (int it = 0; it < 8; it++) {
            int f = tid + it * 256;
            float4 v = g4[f];
            int r = f >> 4, k4 = (f & 15) * 4;
            u32 off = (u32)(r * ASTR + k4 * 2);
            u32 h0, l0, h1, l1;
            split2(v.x, v.y, h0, l0);
            split2(v.z, v.w, h1, l1);
            *(ull*)(smem + OFF_A1 + off) = (ull)h0 | ((ull)h1 << 32);
            *(ull*)(smem + OFF_A2 + off) = (ull)l0 | ((ull)l1 << 32);
        }
        const float4* x4 = (const float4*)(ext + ebase * 32);     // k 64..95
#pragma unroll
        for (int it = 0; it < 4; it++) {
            int f = tid + it * 256;
            float4 v = x4[f];
            int r = f >> 3, k4 = 64 + (f & 7) * 4;
            u32 off = (u32)(r * ASTR + k4 * 2);
            u32 h0, l0, h1, l1;
            split2(v.x, v.y, h0, l0);
            split2(v.z, v.w, h1, l1);
            *(ull*)(smem + OFF_A1 + off) = (ull)h0 | ((ull)h1 << 32);
            *(ull*)(smem + OFF_A2 + off) = (ull)l0 | ((ull)l1 << 32);
        }
        // B tiles: linear copy (prep2 layout == smem layout)
        const float4* mb0 = (const float4*)g_Mb[0];
        const float4* mb1 = (const float4*)g_Mb[1];
#pragma unroll
        for (int it = 0; it < 4; it++) {
            int f = tid + it * 256;
            if (f < 832) {
                ((float4*)(smem + OFF_B1))[f] = mb0[f];
                ((float4*)(smem + OFF_B2))[f] = mb1[f];
            }
        }
    }
    __syncthreads();

    // -- MMA mainloop: warp (wm, wn) tile 32x32; 3 passes x 6 k16-chunks --
    int wm = (wid & 3) * 32, wn = (wid >> 2) * 32;
    float acc[2][4][4];
#pragma unroll
    for (int mt = 0; mt < 2; mt++)
#pragma unroll
        for (int nt = 0; nt < 4; nt++)
#pragma unroll
            for (int i = 0; i < 4; i++) acc[mt][nt][i] = 0.f;

    u32 arow = (u32)((wm + (lane & 15)) * ASTR + (lane >> 4) * 16);
    u32 brow = (u32)((wn + (lane & 15)) * ASTR + (lane >> 4) * 16);

#pragma unroll
    for (int p = 0; p < 3; p++) {
        u32 abase = sb + (p == 2 ? OFF_A2 : OFF_A1) + arow;
        u32 bbase = sb + (p == 1 ? OFF_B2 : OFF_B1) + brow;
#pragma unroll
        for (int c = 0; c < 6; c++) {
            u32 a[2][4], bm[4][2];
#pragma unroll
            for (int mt = 0; mt < 2; mt++)
                ldsm4(a[mt][0], a[mt][1], a[mt][2], a[mt][3],
                      abase + mt * (16 * ASTR) + c * 32);
#pragma unroll
            for (int half = 0; half < 2; half++) {
                u32 m0, m1, m2, m3;
                ldsm4(m0, m1, m2, m3, bbase + half * (16 * ASTR) + c * 32);
                bm[half * 2 + 0][0] = m0; bm[half * 2 + 0][1] = m2;
                bm[half * 2 + 1][0] = m1; bm[half * 2 + 1][1] = m3;
            }
#pragma unroll
            for (int mt = 0; mt < 2; mt++)
#pragma unroll
                for (int nt = 0; nt < 4; nt++)
                    mma16816(acc[mt][nt], a[mt], bm[nt]);
        }
    }
    __syncthreads();   // A/B smem dead; staging overlays it

    // -- write accs to f32 staging (XOR-staggered 16B chunks per row) --
#pragma unroll
    for (int mt = 0; mt < 2; mt++) {
        int r0 = wm + mt * 16 + (lane >> 2);
#pragma unroll
        for (int nt = 0; nt < 4; nt++) {
            int n0 = wn + nt * 8 + 2 * (lane & 3);
#pragma unroll
            for (int half = 0; half < 2; half++) {
                int r = r0 + half * 8;
                u32 off = (u32)(r * 256 + (((n0 >> 2) ^ (r & 7)) << 4) + (n0 & 3) * 4);
                *(float2*)(smem + off) = make_float2(acc[mt][nt][half * 2],
                                                     acc[mt][nt][half * 2 + 1]);
            }
        }
    }
    __syncthreads();

    // -- coalesced epilogue: stage + P'[src] + Q[dst], relu, store --
    {
        float4* o4 = (float4*)(out + ebase * 64);
#pragma unroll
        for (int it = 0; it < 8; it++) {
            int f = tid + it * 256;
            int r = f >> 4, c4 = f & 15;
            float4 v = *(const float4*)(smem + r * 256 + ((c4 ^ (r & 7)) << 4));
            int s = sidx[r], d = didx[r];
            float4 p = *(const float4*)(g_P + (size_t)s * 64 + c4 * 4);
            float4 q = *(const float4*)(g_Q + (size_t)d * 64 + c4 * 4);
            float4 o;
            o.x = fmaxf(v.x + p.x + q.x, 0.f);
            o.y = fmaxf(v.y + p.y + q.y, 0.f);
            o.z = fmaxf(v.z + p.z + q.z, 0.f);
            o.w = fmaxf(v.w + p.w + q.w, 0.f);
            o4[f] = o;
        }
    }
}

extern "C" void kernel_launch(void* const* d_in, const int* in_sizes, int n_in,
                              void* d_out, int out_size) {
    const float* h    = (const float*)d_in[0];
    const float* e_h  = (const float*)d_in[1];
    const float* extf = (const float*)d_in[2];
    const float* W1   = (const float*)d_in[3];
    const float* b1   = (const float*)d_in[4];
    const float* W2   = (const float*)d_in[5];
    const float* b2   = (const float*)d_in[6];
    const int* src    = (const int*)d_in[7];
    const int* dst    = (const int*)d_in[8];
    float* out = (float*)d_out;

    const int node_smem = (64 * SH_STR + 64 * 128) * 4;        // 50176 B
    cudaFuncSetAttribute(node_kernel, cudaFuncAttributeMaxDynamicSharedMemorySize, node_smem);
    cudaFuncSetAttribute(edge_kernel, cudaFuncAttributeMaxDynamicSharedMemorySize, EDGE_SMEM);

    prep_kernel<<<64, 128>>>(W1, b1, W2, b2);
    prep2_kernel<<<12, 256>>>();
    node_kernel<<<(N_NODES + 63) / 64, 256, node_smem>>>(h);
    edge_kernel<<<N_EDGES / 128, 256, EDGE_SMEM>>>(e_h, extf, src, dst, out);
}

// round 10
// speedup vs baseline: 3.0321x; 1.1745x over previous
#include <cuda_runtime.h>
#include <cstdint>

// EventMessagePassingEdge: out = relu([h[src]|e_h|h[dst]]@W1+b1 | ext] @ W2 + b2)
// Folded:  out = relu( P'[src] + Q[dst] + [e_h|ext] @ M )      (c folded into P')
// Edge stage = bf16 mma.sync (m16n8k16) with 2-term operand splitting:
//   A=A1+A2, B=B1+B2 (bf16); D ~= A1B1 + A1B2 + A2B1 accumulated in fp32.
// R10: 512-thr CTA, 16 warps (8x2), warp tile 16x32, fused single-sweep fragments
// (A1/A2/B1/B2 ldmatrix'd once per k-chunk) -> 2x occupancy, -33% LDSM traffic.

#define N_NODES 50000
#define N_EDGES 800000
#define HID 64
#define EXT 32
#define SH_STR 68

typedef unsigned long long ull;
typedef unsigned int u32;

// ---- device scratch (no allocations allowed) ----
__device__ float g_P[N_NODES * HID];                 // h @ (W1a@W2a) + c
__device__ float g_Q[N_NODES * HID];                 // h @ (W1c@W2a)
__device__ float g_M[(HID + EXT) * HID];             // [k][n]
__device__ float g_Wn[HID * 2 * HID];                // node-stage weights
__device__ float g_c[HID];                           // b1@W2a + b2
__device__ __align__(16) u32 g_Mb[2][64 * 52];       // B split, n-major [64][104 bf16]

// ---- helpers ----
__device__ __forceinline__ u32 smem_u32(const void* p) {
    u32 a; asm("{ .reg .u64 t; cvta.to.shared.u64 t, %1; cvt.u32.u64 %0, t; }" : "=r"(a) : "l"(p));
    return a;
}
__device__ __forceinline__ void split2(float v0, float v1, u32& hi, u32& lo) {
    asm("cvt.rn.bf16x2.f32 %0, %1, %2;" : "=r"(hi) : "f"(v1), "f"(v0));   // lo16=v0, hi16=v1
    float h0 = __uint_as_float(hi << 16);
    float h1 = __uint_as_float(hi & 0xffff0000u);
    float r0 = v0 - h0, r1 = v1 - h1;
    asm("cvt.rn.bf16x2.f32 %0, %1, %2;" : "=r"(lo) : "f"(r1), "f"(r0));
}

// ---- packed f32x2 helpers (node kernel) ----
__device__ __forceinline__ ull pk2(float lo, float hi) {
    ull r; asm("mov.b64 %0, {%1, %2};" : "=l"(r) : "f"(lo), "f"(hi)); return r;
}
__device__ __forceinline__ void upk2(ull v, float& lo, float& hi) {
    asm("mov.b64 {%0, %1}, %2;" : "=f"(lo), "=f"(hi) : "l"(v));
}
__device__ __forceinline__ ull splat(float v) {
    ull r; asm("mov.b64 %0, {%1, %1};" : "=l"(r) : "f"(v)); return r;
}
__device__ __forceinline__ ull ffma2(ull a, ull b, ull c) {
    ull d; asm("fma.rn.f32x2 %0, %1, %2, %3;" : "=l"(d) : "l"(a), "l"(b), "l"(c)); return d;
}

// ---- mma.sync primitives ----
__device__ __forceinline__ void ldsm4(u32& r0, u32& r1, u32& r2, u32& r3, u32 addr) {
    asm volatile("ldmatrix.sync.aligned.m8n8.x4.shared.b16 {%0,%1,%2,%3}, [%4];"
                 : "=r"(r0), "=r"(r1), "=r"(r2), "=r"(r3) : "r"(addr));
}
__device__ __forceinline__ void mma16816(float* c, const u32* a, u32 b0, u32 b1) {
    asm volatile("mma.sync.aligned.m16n8k16.row.col.f32.bf16.bf16.f32 "
                 "{%0,%1,%2,%3}, {%4,%5,%6,%7}, {%8,%9}, {%0,%1,%2,%3};"
                 : "+f"(c[0]), "+f"(c[1]), "+f"(c[2]), "+f"(c[3])
                 : "r"(a[0]), "r"(a[1]), "r"(a[2]), "r"(a[3]), "r"(b0), "r"(b1));
}

// ---- Stage 0: fold weight matrices ----
__global__ void prep_kernel(const float* __restrict__ W1, const float* __restrict__ b1,
                            const float* __restrict__ W2, const float* __restrict__ b2) {
    int t = blockIdx.x * blockDim.x + threadIdx.x;
    int stride = gridDim.x * blockDim.x;
    for (int i = t; i < HID * HID; i += stride) {             // Wsrc = W1a @ W2a
        int k = i >> 6, j = i & 63;
        float s = 0.f;
        for (int x = 0; x < HID; x++) s += W1[k * HID + x] * W2[x * HID + j];
        g_Wn[k * 128 + j] = s;
    }
    for (int i = t; i < HID * HID; i += stride) {             // Wdst = W1c @ W2a
        int k = i >> 6, j = i & 63;
        float s = 0.f;
        for (int x = 0; x < HID; x++) s += W1[(128 + k) * HID + x] * W2[x * HID + j];
        g_Wn[k * 128 + 64 + j] = s;
    }
    for (int i = t; i < HID * HID; i += stride) {             // M1 = W1b @ W2a
        int k = i >> 6, j = i & 63;
        float s = 0.f;
        for (int x = 0; x < HID; x++) s += W1[(64 + k) * HID + x] * W2[x * HID + j];
        g_M[k * HID + j] = s;
    }
    for (int i = t; i < EXT * HID; i += stride) {             // copy W2b
        g_M[HID * HID + i] = W2[HID * HID + i];
    }
    for (int j = t; j < HID; j += stride) {                   // c = b1@W2a + b2
        float s = b2[j];
        for (int x = 0; x < HID; x++) s += b1[x] * W2[x * HID + j];
        g_c[j] = s;
    }
}

// ---- Stage 0b: split B = M^T into bf16 hi/lo, n-major [64][104] ----
__global__ void prep2_kernel() {
    int t = blockIdx.x * blockDim.x + threadIdx.x;    // 64 n x 48 k-pairs
    if (t >= 64 * 48) return;
    int n = t & 63, kp = t >> 6;
    float v0 = g_M[(2 * kp) * HID + n];
    float v1 = g_M[(2 * kp + 1) * HID + n];
    u32 hi, lo;
    split2(v0, v1, hi, lo);
    g_Mb[0][n * 52 + kp] = hi;
    g_Mb[1][n * 52 + kp] = lo;
}

// ---- Stage 1: node precompute, tiled FFMA2 GEMM [50000x64] @ [64x128] -> P|Q ----
__global__ void __launch_bounds__(256) node_kernel(const float* __restrict__ h) {
    extern __shared__ char dynsmem[];
    float* sH = (float*)dynsmem;              // [64][SH_STR]
    float* sW = sH + 64 * SH_STR;             // [64][128]
    int tid = threadIdx.x;
    int og = tid & 15;
    int ng = tid >> 4;
    int nb = blockIdx.x * 64;

    {
        const float4* h4 = (const float4*)h;
#pragma unroll
        for (int r = 0; r < 4; r++) {
            int t4 = tid + r * 256;
            int n = t4 >> 4, k = (t4 & 15) * 4;
            float4 v = make_float4(0.f, 0.f, 0.f, 0.f);
            if (nb + n < N_NODES) v = h4[(size_t)(nb + n) * 16 + (t4 & 15)];
            *(float4*)(sH + n * SH_STR + k) = v;
        }
        const float4* w4 = (const float4*)g_Wn;
#pragma unroll
        for (int r = 0; r < 8; r++) {
            int t4 = tid + r * 256;
            ((float4*)sW)[t4] = w4[t4];
        }
    }
    __syncthreads();

    ull acc[4][4];
#pragma unroll
    for (int i = 0; i < 4; i++)
#pragma unroll
        for (int j = 0; j < 4; j++) acc[i][j] = 0ull;

#pragma unroll 2
    for (int kk = 0; kk < 16; kk++) {
        float4 a[4];
#pragma unroll
        for (int i = 0; i < 4; i++)
            a[i] = *(const float4*)(sH + (ng + 16 * i) * SH_STR + kk * 4);
#pragma unroll
        for (int j = 0; j < 4; j++) {
            int k = kk * 4 + j;
            ulonglong2 b0 = *(const ulonglong2*)(sW + k * 128 + 4 * og);
            ulonglong2 b1 = *(const ulonglong2*)(sW + k * 128 + 64 + 4 * og);
#pragma unroll
            for (int i = 0; i < 4; i++) {
                float av = (j == 0) ? a[i].x : (j == 1) ? a[i].y : (j == 2) ? a[i].z : a[i].w;
                ull vv = splat(av);
                acc[i][0] = ffma2(vv, b0.x, acc[i][0]);
                acc[i][1] = ffma2(vv, b0.y, acc[i][1]);
                acc[i][2] = ffma2(vv, b1.x, acc[i][2]);
                acc[i][3] = ffma2(vv, b1.y, acc[i][3]);
            }
        }
    }

    float4 c4 = *(const float4*)(g_c + 4 * og);   // fold bias-vector c into P
#pragma unroll
    for (int i = 0; i < 4; i++) {
        int n = nb + ng + 16 * i;
        if (n < N_NODES) {
            float a, b, c, d;
            upk2(acc[i][0], a, b); upk2(acc[i][1], c, d);
            *(float4*)(g_P + (size_t)n * 64 + 4 * og) =
                make_float4(a + c4.x, b + c4.y, c + c4.z, d + c4.w);
            upk2(acc[i][2], a, b); upk2(acc[i][3], c, d);
            *(float4*)(g_Q + (size_t)n * 64 + 4 * og) = make_float4(a, b, c, d);
        }
    }
}

// ---- Stage 2: edge kernel — bf16x3 mma.sync GEMM, 512 thr, fused fragments ----
// smem layout (bytes):
//   A1 @ 0      (128 x 208B = 26624)   bf16 [128][104], k contiguous
//   A2 @ 26624  (26624)
//   B1 @ 53248  (64 x 208B = 13312)    bf16 [64][104] n-major
//   B2 @ 66560  (13312)
//   idx @ 79872 (1024)                  src[128], dst[128]
//   staging (f32 128x64, XOR-staggered) overlays A1/A2 after the MMA phase.
#define ASTR 208
#define OFF_A1 0
#define OFF_A2 26624
#define OFF_B1 53248
#define OFF_B2 66560
#define OFF_IDX 79872
#define EDGE_SMEM 80896

__global__ void __launch_bounds__(512, 2) edge_kernel(const float* __restrict__ e_h,
                                                      const float* __restrict__ ext,
                                                      const int* __restrict__ src,
                                                      const int* __restrict__ dst,
                                                      float* __restrict__ out) {
    extern __shared__ char dynsmem[];
    char* smem = dynsmem;
    u32 sb = smem_u32(smem);
    int tid = threadIdx.x, wid = tid >> 5, lane = tid & 31;
    size_t ebase = (size_t)blockIdx.x * 128;
    int* sidx = (int*)(smem + OFF_IDX);
    int* didx = sidx + 128;

    // -- stage indices --
    if (tid < 128) sidx[tid] = src[ebase + tid];
    else if (tid < 256) didx[tid - 128] = dst[ebase + (tid - 128)];

    // -- stage A: load fp32, split into bf16 hi/lo tiles --
    {
        const float4* g4 = (const float4*)(e_h + ebase * 64);     // k 0..63
#pragma unroll
        for (int it = 0; it < 4; it++) {
            int f = tid + it * 512;
            float4 v = g4[f];
            int r = f >> 4, k4 = (f & 15) * 4;
            u32 off = (u32)(r * ASTR + k4 * 2);
            u32 h0, l0, h1, l1;
            split2(v.x, v.y, h0, l0);
            split2(v.z, v.w, h1, l1);
            *(ull*)(smem + OFF_A1 + off) = (ull)h0 | ((ull)h1 << 32);
            *(ull*)(smem + OFF_A2 + off) = (ull)l0 | ((ull)l1 << 32);
        }
        const float4* x4 = (const float4*)(ext + ebase * 32);     // k 64..95
#pragma unroll
        for (int it = 0; it < 2; it++) {
            int f = tid + it * 512;
            float4 v = x4[f];
            int r = f >> 3, k4 = 64 + (f & 7) * 4;
            u32 off = (u32)(r * ASTR + k4 * 2);
            u32 h0, l0, h1, l1;
            split2(v.x, v.y, h0, l0);
            split2(v.z, v.w, h1, l1);
            *(ull*)(smem + OFF_A1 + off) = (ull)h0 | ((ull)h1 << 32);
            *(ull*)(smem + OFF_A2 + off) = (ull)l0 | ((ull)l1 << 32);
        }
        // B tiles: linear copy (prep2 layout == smem layout)
        const float4* mb0 = (const float4*)g_Mb[0];
        const float4* mb1 = (const float4*)g_Mb[1];
#pragma unroll
        for (int it = 0; it < 2; it++) {
            int f = tid + it * 512;
            if (f < 832) {
                ((float4*)(smem + OFF_B1))[f] = mb0[f];
                ((float4*)(smem + OFF_B2))[f] = mb1[f];
            }
        }
    }
    __syncthreads();

    // -- MMA mainloop: warp (wm, wn); warp tile 16x32; fused 3-term per k16 chunk --
    int wm = (wid & 7) * 16, wn = (wid >> 3) * 32;
    float acc[4][4];
#pragma unroll
    for (int nt = 0; nt < 4; nt++)
#pragma unroll
        for (int i = 0; i < 4; i++) acc[nt][i] = 0.f;

    u32 arow  = sb + (u32)((wm + (lane & 15)) * ASTR + (lane >> 4) * 16);
    u32 brow0 = sb + (u32)((wn + (lane & 15)) * ASTR + (lane >> 4) * 16);
    u32 brow1 = brow0 + 16 * ASTR;

#pragma unroll
    for (int c = 0; c < 6; c++) {
        u32 co = (u32)(c * 32);
        u32 a1[4], a2[4], b1[4][2], b2[4][2];
        ldsm4(a1[0], a1[1], a1[2], a1[3], arow + OFF_A1 + co);
        ldsm4(a2[0], a2[1], a2[2], a2[3], arow + OFF_A2 + co);
        {
            u32 m0, m1, m2, m3;
            ldsm4(m0, m1, m2, m3, brow0 + OFF_B1 + co);
            b1[0][0] = m0; b1[0][1] = m2; b1[1][0] = m1; b1[1][1] = m3;
            ldsm4(m0, m1, m2, m3, brow1 + OFF_B1 + co);
            b1[2][0] = m0; b1[2][1] = m2; b1[3][0] = m1; b1[3][1] = m3;
            ldsm4(m0, m1, m2, m3, brow0 + OFF_B2 + co);
            b2[0][0] = m0; b2[0][1] = m2; b2[1][0] = m1; b2[1][1] = m3;
            ldsm4(m0, m1, m2, m3, brow1 + OFF_B2 + co);
            b2[2][0] = m0; b2[2][1] = m2; b2[3][0] = m1; b2[3][1] = m3;
        }
#pragma unroll
        for (int nt = 0; nt < 4; nt++) {
            mma16816(acc[nt], a1, b1[nt][0], b1[nt][1]);
            mma16816(acc[nt], a1, b2[nt][0], b2[nt][1]);
            mma16816(acc[nt], a2, b1[nt][0], b1[nt][1]);
        }
    }
    __syncthreads();   // A/B smem dead; staging overlays it

    // -- write accs to f32 staging (XOR-staggered 16B chunks per row) --
    {
        int r0 = wm + (lane >> 2);
#pragma unroll
        for (int nt = 0; nt < 4; nt++) {
            int n0 = wn + nt * 8 + 2 * (lane & 3);
#pragma unroll
            for (int half = 0; half < 2; half++) {
                int r = r0 + half * 8;
                u32 off = (u32)(r * 256 + (((n0 >> 2) ^ (r & 7)) << 4) + (n0 & 3) * 4);
                *(float2*)(smem + off) = make_float2(acc[nt][half * 2],
                                                     acc[nt][half * 2 + 1]);
            }
        }
    }
    __syncthreads();

    // -- coalesced epilogue: stage + P'[src] + Q[dst], relu, store --
    {
        float4* o4 = (float4*)(out + ebase * 64);
#pragma unroll
        for (int it = 0; it < 4; it++) {
            int f = tid + it * 512;
            int r = f >> 4, c4 = f & 15;
            float4 v = *(const float4*)(smem + r * 256 + ((c4 ^ (r & 7)) << 4));
            int s = sidx[r], d = didx[r];
            float4 p = *(const float4*)(g_P + (size_t)s * 64 + c4 * 4);
            float4 q = *(const float4*)(g_Q + (size_t)d * 64 + c4 * 4);
            float4 o;
            o.x = fmaxf(v.x + p.x + q.x, 0.f);
            o.y = fmaxf(v.y + p.y + q.y, 0.f);
            o.z = fmaxf(v.z + p.z + q.z, 0.f);
            o.w = fmaxf(v.w + p.w + q.w, 0.f);
            o4[f] = o;
        }
    }
}

extern "C" void kernel_launch(void* const* d_in, const int* in_sizes, int n_in,
                              void* d_out, int out_size) {
    const float* h    = (const float*)d_in[0];
    const float* e_h  = (const float*)d_in[1];
    const float* extf = (const float*)d_in[2];
    const float* W1   = (const float*)d_in[3];
    const float* b1   = (const float*)d_in[4];
    const float* W2   = (const float*)d_in[5];
    const float* b2   = (const float*)d_in[6];
    const int* src    = (const int*)d_in[7];
    const int* dst    = (const int*)d_in[8];
    float* out = (float*)d_out;

    const int node_smem = (64 * SH_STR + 64 * 128) * 4;        // 50176 B
    cudaFuncSetAttribute(node_kernel, cudaFuncAttributeMaxDynamicSharedMemorySize, node_smem);
    cudaFuncSetAttribute(edge_kernel, cudaFuncAttributeMaxDynamicSharedMemorySize, EDGE_SMEM);

    prep_kernel<<<64, 128>>>(W1, b1, W2, b2);
    prep2_kernel<<<12, 256>>>();
    node_kernel<<<(N_NODES + 63) / 64, 256, node_smem>>>(h);
    edge_kernel<<<N_EDGES / 128, 512, EDGE_SMEM>>>(e_h, extf, src, dst, out);
}